// round 3
// baseline (speedup 1.0000x reference)
#include <cuda_runtime.h>
#include <cstddef>

#define T_STEPS 8192
#define CHUNK   1024
#define NRES    2048
#define DIN     64
#define DOUT    64
#define GBLK    128          // CTAs; 16 rows each
#define TPB     256
#define LEAK    0.3f
#define NOISE_L 0.01f
#define TILE_T  128

// ---------------- scratch (device globals: allocation-free) ----------------
__device__ float g_drive [T_STEPS * NRES];     // 64 MB
__device__ float g_states[T_STEPS * NRES];     // 64 MB
__device__ float g_sbuf  [2][NRES];            // double-buffered state values
__device__ int   g_tag   [GBLK];               // per-producer-CTA step tag

// ---------------- kernel 0: reset exchange state (determinism) --------------
__global__ void init_kernel() {
    int i = blockIdx.x * blockDim.x + threadIdx.x;
    if (i < NRES) { g_sbuf[0][i] = 0.f; g_sbuf[1][i] = 0.f; }
    if (i < GBLK) g_tag[i] = 0;
}

// ---------------- kernel 1: drive = u @ W_in^T + 0.01*noise -----------------
__global__ void drive_kernel(const float* __restrict__ u,
                             const float* __restrict__ noise,
                             const float* __restrict__ W_in) {
    __shared__ float4 u_sh[TILE_T * (DIN / 4)];
    const int n  = blockIdx.x * 256 + threadIdx.x;
    const int t0 = blockIdx.y * TILE_T;

    float4 w[DIN / 4];
    const float4* Wv = reinterpret_cast<const float4*>(W_in);
    #pragma unroll
    for (int j = 0; j < DIN / 4; j++) w[j] = Wv[(size_t)n * (DIN / 4) + j];

    const float4* uv = reinterpret_cast<const float4*>(u + (size_t)t0 * DIN);
    for (int i = threadIdx.x; i < TILE_T * (DIN / 4); i += 256) u_sh[i] = uv[i];
    __syncthreads();

    for (int t = 0; t < TILE_T; t++) {
        float acc = 0.f;
        #pragma unroll
        for (int j = 0; j < DIN / 4; j++) {
            float4 uu = u_sh[t * (DIN / 4) + j];
            acc += w[j].x * uu.x + w[j].y * uu.y + w[j].z * uu.z + w[j].w * uu.w;
        }
        size_t idx = (size_t)(t0 + t) * NRES + n;
        g_drive[idx] = acc + NOISE_L * noise[idx];
    }
}

// ---------------- kernel 2: reservoir recurrence chunk ----------------------
// 128 CTAs x 256 thr; CTA owns 16 rows; warp owns 2 rows; lane owns 64 cols.
// Sync: producer stores 16 floats -> bar.sync -> one st.release tag.
// Consumers acquire-poll per-producer tags, pull 64B each as it becomes ready.
__global__ void __launch_bounds__(TPB, 1) reservoir_kernel(const float* __restrict__ W,
                                                           int t0) {
    __shared__ float s_sh[NRES];               // 8 KB staged state

    const int tid  = threadIdx.x;
    const int cta  = blockIdx.x;
    const int warp = tid >> 5;
    const int lane = tid & 31;
    const int r0   = cta * 16 + warp * 2;
    const int r1   = r0 + 1;

    // One-time: load W slice, pack column pairs into 64-bit (f32x2) registers
    const float4* Wv = reinterpret_cast<const float4*>(W);
    unsigned long long w0[32], w1[32];
    #pragma unroll
    for (int j = 0; j < 16; j++) {
        float4 a = Wv[(size_t)r0 * (NRES / 4) + lane + 32 * j];
        float4 b = Wv[(size_t)r1 * (NRES / 4) + lane + 32 * j];
        w0[2*j]   = ((unsigned long long)__float_as_uint(a.y) << 32) | __float_as_uint(a.x);
        w0[2*j+1] = ((unsigned long long)__float_as_uint(a.w) << 32) | __float_as_uint(a.z);
        w1[2*j]   = ((unsigned long long)__float_as_uint(b.y) << 32) | __float_as_uint(b.x);
        w1[2*j+1] = ((unsigned long long)__float_as_uint(b.w) << 32) | __float_as_uint(b.z);
    }

    // Chunk entry: all tags == t0 (stream order), so s(t0) is in g_sbuf[t0&1]
    float2 sp = make_float2(0.f, 0.f);
    if (lane == 0) {
        sp.x = __ldcg(&g_sbuf[t0 & 1][r0]);
        sp.y = __ldcg(&g_sbuf[t0 & 1][r1]);
    }
    float2 dcur = make_float2(0.f, 0.f);
    if (lane == 0) dcur = *reinterpret_cast<const float2*>(&g_drive[(size_t)t0 * NRES + r0]);

    // Staging assignment: thread i pulls half of producer p = i>>1's 16 floats
    const int p    = tid >> 1;
    const int half = tid & 1;
    const int sidx = p * 4 + half * 2;         // float4 index into state buffer

    #pragma unroll 1
    for (int t = t0; t < t0 + CHUNK; t++) {
        // ---- stage s(t): acquire-poll this thread's producer tag ----------
        int tg;
        do {
            asm volatile("ld.acquire.gpu.global.b32 %0, [%1];"
                         : "=r"(tg) : "l"(g_tag + p));
        } while (tg < t);
        const float4* sin = reinterpret_cast<const float4*>(g_sbuf[t & 1]);
        float4 v0 = __ldcg(&sin[sidx]);
        float4 v1 = __ldcg(&sin[sidx + 1]);
        *reinterpret_cast<float4*>(&s_sh[sidx * 4])     = v0;
        *reinterpret_cast<float4*>(&s_sh[sidx * 4 + 4]) = v1;
        __syncthreads();

        // prefetch next step's drive (hides DRAM latency behind compute)
        float2 dnext = dcur;
        if (lane == 0 && t + 1 < T_STEPS)
            dnext = *reinterpret_cast<const float2*>(&g_drive[(size_t)(t + 1) * NRES + r0]);

        // ---- packed f32x2 mat-vec partials --------------------------------
        const float4* s4 = reinterpret_cast<const float4*>(s_sh);
        unsigned long long acc0a = 0, acc0b = 0, acc1a = 0, acc1b = 0;
        #pragma unroll
        for (int j = 0; j < 16; j++) {
            float4 sv = s4[lane + 32 * j];
            asm("{\n\t"
                ".reg .b64 sA, sB;\n\t"
                "mov.b64 sA, {%4, %5};\n\t"
                "mov.b64 sB, {%6, %7};\n\t"
                "fma.rn.f32x2 %0, %8, sA, %0;\n\t"
                "fma.rn.f32x2 %1, %9, sB, %1;\n\t"
                "fma.rn.f32x2 %2, %10, sA, %2;\n\t"
                "fma.rn.f32x2 %3, %11, sB, %3;\n\t"
                "}"
                : "+l"(acc0a), "+l"(acc0b), "+l"(acc1a), "+l"(acc1b)
                : "f"(sv.x), "f"(sv.y), "f"(sv.z), "f"(sv.w),
                  "l"(w0[2*j]), "l"(w0[2*j+1]), "l"(w1[2*j]), "l"(w1[2*j+1]));
        }
        float e0, o0, e1, o1;
        asm("{\n\t.reg .b64 t0r;\n\tadd.rn.f32x2 t0r, %2, %3;\n\tmov.b64 {%0, %1}, t0r;\n\t}"
            : "=f"(e0), "=f"(o0) : "l"(acc0a), "l"(acc0b));
        asm("{\n\t.reg .b64 t1r;\n\tadd.rn.f32x2 t1r, %2, %3;\n\tmov.b64 {%0, %1}, t1r;\n\t}"
            : "=f"(e1), "=f"(o1) : "l"(acc1a), "l"(acc1b));
        float acc0 = e0 + o0;
        float acc1 = e1 + o1;
        #pragma unroll
        for (int off = 16; off > 0; off >>= 1) {
            acc0 += __shfl_xor_sync(0xffffffffu, acc0, off);
            acc1 += __shfl_xor_sync(0xffffffffu, acc1, off);
        }

        // ---- update + publish ---------------------------------------------
        if (lane == 0) {
            float ns0 = (1.f - LEAK) * sp.x + LEAK * tanhf(dcur.x + acc0);
            float ns1 = (1.f - LEAK) * sp.y + LEAK * tanhf(dcur.y + acc1);
            sp = make_float2(ns0, ns1);
            *reinterpret_cast<float2*>(&g_sbuf[(t + 1) & 1][r0]) = sp;
            *reinterpret_cast<float2*>(&g_states[(size_t)t * NRES + r0]) = sp;
            dcur = dnext;
        }
        __syncthreads();   // orders all warps' publishes before tag release;
                           // also protects s_sh for next iteration's staging
        if (tid == 0)
            asm volatile("st.release.gpu.global.b32 [%0], %1;"
                         :: "l"(g_tag + cta), "r"(t + 1) : "memory");
    }
}

// ---------------- kernel 3: out = states @ w_out^T + b_out ------------------
__global__ void proj_kernel(const float* __restrict__ w_out,
                            const float* __restrict__ b_out,
                            float* __restrict__ out) {
    __shared__ float s_sh[64][33];
    __shared__ float w_sh[DOUT][33];
    const int t0  = blockIdx.x * 64;
    const int tid = threadIdx.x;
    const int tx  = tid & 15;
    const int ty  = tid >> 4;
    float acc[4][4] = {};

    for (int kc = 0; kc < NRES; kc += 32) {
        for (int i = tid; i < 64 * 32; i += 256) {
            int r = i >> 5, k = i & 31;
            s_sh[r][k] = g_states[(size_t)(t0 + r) * NRES + kc + k];
        }
        for (int i = tid; i < DOUT * 32; i += 256) {
            int o = i >> 5, k = i & 31;
            w_sh[o][k] = w_out[(size_t)o * NRES + kc + k];
        }
        __syncthreads();
        for (int k = 0; k < 32; k++) {
            float sv[4], wv[4];
            #pragma unroll
            for (int i = 0; i < 4; i++) sv[i] = s_sh[ty * 4 + i][k];
            #pragma unroll
            for (int j = 0; j < 4; j++) wv[j] = w_sh[tx * 4 + j][k];
            #pragma unroll
            for (int i = 0; i < 4; i++)
                #pragma unroll
                for (int j = 0; j < 4; j++)
                    acc[i][j] += sv[i] * wv[j];
        }
        __syncthreads();
    }
    #pragma unroll
    for (int i = 0; i < 4; i++)
        #pragma unroll
        for (int j = 0; j < 4; j++)
            out[(size_t)(t0 + ty * 4 + i) * DOUT + tx * 4 + j] = acc[i][j] + b_out[tx * 4 + j];
}

// ---------------- launch ----------------------------------------------------
extern "C" void kernel_launch(void* const* d_in, const int* in_sizes, int n_in,
                              void* d_out, int out_size) {
    const float* u     = (const float*)d_in[0];  // (8192, 64)
    const float* noise = (const float*)d_in[1];  // (8192, 2048)
    const float* W_in  = (const float*)d_in[2];  // (2048, 64)
    const float* W     = (const float*)d_in[3];  // (2048, 2048)
    const float* w_out = (const float*)d_in[4];  // (64, 2048)
    const float* b_out = (const float*)d_in[5];  // (64,)
    float* out = (float*)d_out;                  // (8192, 64)

    init_kernel<<<NRES / 256, 256>>>();
    drive_kernel<<<dim3(NRES / 256, T_STEPS / TILE_T), 256>>>(u, noise, W_in);
    for (int c = 0; c < T_STEPS / CHUNK; c++)
        reservoir_kernel<<<GBLK, TPB>>>(W, c * CHUNK);   // 8 launches -> ncu hits one
    proj_kernel<<<T_STEPS / 64, 256>>>(w_out, b_out, out);
}

// round 4
// speedup vs baseline: 2.1135x; 2.1135x over previous
#include <cuda_runtime.h>
#include <cstddef>

#define T_STEPS 8192
#define NRES    2048
#define DIN     64
#define DOUT    64
#define GBLK    128          // CTAs; 16 rows each
#define TPB     256
#define LEAK    0.3f
#define NOISE_L 0.01f
#define TILE_T  128

// ---------------- scratch (device globals: allocation-free) ----------------
__device__ float g_drive [T_STEPS * NRES];              // 64 MB
__device__ float g_states[T_STEPS * NRES];              // 64 MB
__device__ unsigned long long g_ex[2][NRES];            // (tag<<32)|valbits, dbl-buffered

// ---------------- kernel 0: reset exchange buffers (determinism) ------------
__global__ void init_kernel() {
    int i = blockIdx.x * blockDim.x + threadIdx.x;
    if (i < NRES) {
        g_ex[0][i] = 0ULL;                   // tag 0 == step 0, value 0.0f
        g_ex[1][i] = 0xFFFFFFFF00000000ULL;  // never-matching tag
    }
}

// ---------------- kernel 1: drive = u @ W_in^T + 0.01*noise -----------------
__global__ void drive_kernel(const float* __restrict__ u,
                             const float* __restrict__ noise,
                             const float* __restrict__ W_in) {
    __shared__ float4 u_sh[TILE_T * (DIN / 4)];
    const int n  = blockIdx.x * 256 + threadIdx.x;
    const int t0 = blockIdx.y * TILE_T;

    float4 w[DIN / 4];
    const float4* Wv = reinterpret_cast<const float4*>(W_in);
    #pragma unroll
    for (int j = 0; j < DIN / 4; j++) w[j] = Wv[(size_t)n * (DIN / 4) + j];

    const float4* uv = reinterpret_cast<const float4*>(u + (size_t)t0 * DIN);
    for (int i = threadIdx.x; i < TILE_T * (DIN / 4); i += 256) u_sh[i] = uv[i];
    __syncthreads();

    for (int t = 0; t < TILE_T; t++) {
        float acc = 0.f;
        #pragma unroll
        for (int j = 0; j < DIN / 4; j++) {
            float4 uu = u_sh[t * (DIN / 4) + j];
            acc += w[j].x * uu.x + w[j].y * uu.y + w[j].z * uu.z + w[j].w * uu.w;
        }
        size_t idx = (size_t)(t0 + t) * NRES + n;
        g_drive[idx] = acc + NOISE_L * noise[idx];
    }
}

// ---------------- kernel 2: persistent reservoir, fence-free sync -----------
// 128 CTAs x 256 thr; CTA owns 16 rows; warp owns 2 rows; lane owns 64 cols.
// Exchange: 8B words carrying (step tag | value). No fences, no atomics.
__global__ void __launch_bounds__(TPB, 1) reservoir_kernel(const float* __restrict__ W) {
    __shared__ float s_sh[NRES];              // 8 KB staged state

    const int tid  = threadIdx.x;
    const int cta  = blockIdx.x;
    const int warp = tid >> 5;
    const int lane = tid & 31;
    const int r0   = cta * 16 + warp * 2;

    // One-time: load W slice, pack column pairs into 64-bit (f32x2) registers
    const float4* Wv = reinterpret_cast<const float4*>(W);
    unsigned long long w0[32], w1[32];
    #pragma unroll
    for (int j = 0; j < 16; j++) {
        float4 a = Wv[(size_t)r0 * (NRES / 4) + lane + 32 * j];
        float4 b = Wv[(size_t)(r0 + 1) * (NRES / 4) + lane + 32 * j];
        w0[2*j]   = ((unsigned long long)__float_as_uint(a.y) << 32) | __float_as_uint(a.x);
        w0[2*j+1] = ((unsigned long long)__float_as_uint(a.w) << 32) | __float_as_uint(a.z);
        w1[2*j]   = ((unsigned long long)__float_as_uint(b.y) << 32) | __float_as_uint(b.x);
        w1[2*j+1] = ((unsigned long long)__float_as_uint(b.w) << 32) | __float_as_uint(b.z);
    }

    float2 sp = make_float2(0.f, 0.f);
    float2 dcur = make_float2(0.f, 0.f);
    if (lane == 0) dcur = *reinterpret_cast<const float2*>(&g_drive[r0]);

    const int wb = tid * 8;                   // this thread's 8 exchange words

    #pragma unroll 1
    for (int t = 0; t < T_STEPS; t++) {
        // ---- stage s(t): vectorized self-validating poll ------------------
        const unsigned long long* ex = &g_ex[t & 1][0];
        const unsigned tag = (unsigned)t;
        unsigned need = 0xFu;                 // 4 pairs of 8B words
        do {
            #pragma unroll
            for (int k = 0; k < 4; k++) {
                if (need & (1u << k)) {
                    unsigned long long qa, qb;
                    asm volatile("ld.volatile.global.v2.u64 {%0,%1}, [%2];"
                                 : "=l"(qa), "=l"(qb) : "l"(ex + wb + 2 * k));
                    if ((unsigned)(qa >> 32) == tag && (unsigned)(qb >> 32) == tag) {
                        float2 f = make_float2(__uint_as_float((unsigned)qa),
                                               __uint_as_float((unsigned)qb));
                        *reinterpret_cast<float2*>(&s_sh[wb + 2 * k]) = f;
                        need &= ~(1u << k);
                    }
                }
            }
        } while (need);
        __syncthreads();

        // prefetch next step's drive (hides DRAM latency behind compute)
        float2 dnext = dcur;
        if (lane == 0 && t + 1 < T_STEPS)
            dnext = *reinterpret_cast<const float2*>(&g_drive[(size_t)(t + 1) * NRES + r0]);

        // ---- packed f32x2 mat-vec partials --------------------------------
        const float4* s4 = reinterpret_cast<const float4*>(s_sh);
        unsigned long long acc0a = 0, acc0b = 0, acc1a = 0, acc1b = 0;
        #pragma unroll
        for (int j = 0; j < 16; j++) {
            float4 sv = s4[lane + 32 * j];
            asm("{\n\t"
                ".reg .b64 sA, sB;\n\t"
                "mov.b64 sA, {%4, %5};\n\t"
                "mov.b64 sB, {%6, %7};\n\t"
                "fma.rn.f32x2 %0, %8, sA, %0;\n\t"
                "fma.rn.f32x2 %1, %9, sB, %1;\n\t"
                "fma.rn.f32x2 %2, %10, sA, %2;\n\t"
                "fma.rn.f32x2 %3, %11, sB, %3;\n\t"
                "}"
                : "+l"(acc0a), "+l"(acc0b), "+l"(acc1a), "+l"(acc1b)
                : "f"(sv.x), "f"(sv.y), "f"(sv.z), "f"(sv.w),
                  "l"(w0[2*j]), "l"(w0[2*j+1]), "l"(w1[2*j]), "l"(w1[2*j+1]));
        }
        float e0, o0, e1, o1;
        asm("{\n\t.reg .b64 t0r;\n\tadd.rn.f32x2 t0r, %2, %3;\n\tmov.b64 {%0, %1}, t0r;\n\t}"
            : "=f"(e0), "=f"(o0) : "l"(acc0a), "l"(acc0b));
        asm("{\n\t.reg .b64 t1r;\n\tadd.rn.f32x2 t1r, %2, %3;\n\tmov.b64 {%0, %1}, t1r;\n\t}"
            : "=f"(e1), "=f"(o1) : "l"(acc1a), "l"(acc1b));
        float acc0 = e0 + o0;
        float acc1 = e1 + o1;
        #pragma unroll
        for (int off = 16; off > 0; off >>= 1) {
            acc0 += __shfl_xor_sync(0xffffffffu, acc0, off);
            acc1 += __shfl_xor_sync(0xffffffffu, acc1, off);
        }

        // ---- update + publish (validity travels in-band; no fences) -------
        if (lane == 0) {
            float ns0 = (1.f - LEAK) * sp.x + LEAK * tanhf(dcur.x + acc0);
            float ns1 = (1.f - LEAK) * sp.y + LEAK * tanhf(dcur.y + acc1);
            sp = make_float2(ns0, ns1);
            unsigned long long ntag = (unsigned long long)(unsigned)(t + 1) << 32;
            unsigned long long p0 = ntag | __float_as_uint(ns0);
            unsigned long long p1 = ntag | __float_as_uint(ns1);
            asm volatile("st.volatile.global.v2.u64 [%0], {%1,%2};"
                         :: "l"(&g_ex[(t + 1) & 1][r0]), "l"(p0), "l"(p1) : "memory");
            *reinterpret_cast<float2*>(&g_states[(size_t)t * NRES + r0]) = sp;
            dcur = dnext;
        }
        __syncthreads();                      // protect s_sh for next staging
    }
}

// ---------------- kernel 3: out = states @ w_out^T + b_out ------------------
// grid: T/32 blocks (256 CTAs); block computes 32 t-rows x 64 outputs
__global__ void proj_kernel(const float* __restrict__ w_out,
                            const float* __restrict__ b_out,
                            float* __restrict__ out) {
    __shared__ float s_sh[32][33];
    __shared__ float w_sh[DOUT][33];
    const int t0  = blockIdx.x * 32;
    const int tid = threadIdx.x;
    const int tx  = tid & 15;                 // output group: 4 outputs
    const int ty  = tid >> 4;                 // t-row group: 2 rows
    float acc[2][4] = {};

    for (int kc = 0; kc < NRES; kc += 32) {
        for (int i = tid; i < 32 * 32; i += 256) {
            int r = i >> 5, k = i & 31;
            s_sh[r][k] = g_states[(size_t)(t0 + r) * NRES + kc + k];
        }
        for (int i = tid; i < DOUT * 32; i += 256) {
            int o = i >> 5, k = i & 31;
            w_sh[o][k] = w_out[(size_t)o * NRES + kc + k];
        }
        __syncthreads();
        for (int k = 0; k < 32; k++) {
            float sv[2], wv[4];
            #pragma unroll
            for (int i = 0; i < 2; i++) sv[i] = s_sh[ty * 2 + i][k];
            #pragma unroll
            for (int j = 0; j < 4; j++) wv[j] = w_sh[tx * 4 + j][k];
            #pragma unroll
            for (int i = 0; i < 2; i++)
                #pragma unroll
                for (int j = 0; j < 4; j++)
                    acc[i][j] += sv[i] * wv[j];
        }
        __syncthreads();
    }
    #pragma unroll
    for (int i = 0; i < 2; i++)
        #pragma unroll
        for (int j = 0; j < 4; j++)
            out[(size_t)(t0 + ty * 2 + i) * DOUT + tx * 4 + j] = acc[i][j] + b_out[tx * 4 + j];
}

// ---------------- launch ----------------------------------------------------
extern "C" void kernel_launch(void* const* d_in, const int* in_sizes, int n_in,
                              void* d_out, int out_size) {
    const float* u     = (const float*)d_in[0];  // (8192, 64)
    const float* noise = (const float*)d_in[1];  // (8192, 2048)
    const float* W_in  = (const float*)d_in[2];  // (2048, 64)
    const float* W     = (const float*)d_in[3];  // (2048, 2048)
    const float* w_out = (const float*)d_in[4];  // (64, 2048)
    const float* b_out = (const float*)d_in[5];  // (64,)
    float* out = (float*)d_out;                  // (8192, 64)

    init_kernel<<<NRES / 256, 256>>>();
    drive_kernel<<<dim3(NRES / 256, T_STEPS / TILE_T), 256>>>(u, noise, W_in);
    reservoir_kernel<<<GBLK, TPB>>>(W);
    proj_kernel<<<T_STEPS / 32, 256>>>(w_out, b_out, out);
}